// round 16
// baseline (speedup 1.0000x reference)
#include <cuda_runtime.h>
#include <cuda_fp16.h>
#include <cstdint>
#include <cstddef>

#define T_STEPS 500
#define BATCH   128
#define NIN     300
#define EDIM    128
#define CDIM    128
#define UDIM    64
#define FDIM    4
#define G3E     384
#define CLIPV   5.0f
#define NROWS   (T_STEPS * BATCH)
#define KGEN    72

// ---------------- scratch (device globals; zero-initialized) ----------------
__device__ float g_xpf[(size_t)NROWS * G3E];
__device__ float g_xpb[(size_t)NROWS * G3E];
__device__ float g_g  [(size_t)NROWS * 2 * EDIM];
__device__ float g_cp [(size_t)NROWS * G3E];

#define XN4   (NROWS * NIN / 4)
#define GN4   (NROWS * 2 * EDIM / 4)
#define WFN4  (G3E * NIN / 4)
#define WCN4  (G3E * (2 * EDIM + NIN) / 4)
#define WMN4  (UDIM * CDIM / 4)
#define WHN4  (G3E * EDIM / 4)         // 12288 : Whh [384,128]
__device__ uint2 g_xh[XN4];
__device__ uint2 g_gh[GN4];
__device__ uint2 g_wfh[WFN4], g_wfl[WFN4];
__device__ uint2 g_wbh[WFN4], g_wbl[WFN4];
__device__ uint2 g_wch[WCN4], g_wcl[WCN4];
__device__ uint2 g_wmh[2 * WMN4], g_wml[2 * WMN4];
__device__ uint2 g_wsh[384 * KGEN / 4], g_wsl[384 * KGEN / 4];
__device__ uint2 g_wWfh[WHN4], g_wWfl[WHN4];   // enc fwd Whh fp16 hi/lo
__device__ uint2 g_wWbh[WHN4], g_wWbl[WHN4];   // enc bwd
__device__ uint2 g_wWch[WHN4], g_wWcl[WHN4];   // ctrl
__device__ uint2 g_hfu[(size_t)NROWS * CDIM / 4];
__device__ uint2 g_genh[(size_t)NROWS * KGEN / 4];
__device__ float g_zero[384];

__device__ __forceinline__ float sigmf(float x) {
    return __fdividef(1.0f, 1.0f + __expf(-x));
}
__device__ __forceinline__ float tanhf_fast(float x) {
    x = fminf(fmaxf(x, -15.f), 15.f);
    float e = __expf(2.0f * x);
    return __fdividef(e - 1.0f, e + 1.0f);
}

// =================================================================================
// fp32 -> fp16 conversions
// =================================================================================
__device__ __forceinline__ uint32_t packh2(__half a, __half b) {
    return ((uint32_t)__half_as_ushort(b) << 16) | __half_as_ushort(a);
}

__global__ __launch_bounds__(256) void conv_half(
    const float4* __restrict__ src, uint2* __restrict__ dst, int n4)
{
    int i = blockIdx.x * 256 + threadIdx.x;
    if (i >= n4) return;
    float4 v = src[i];
    dst[i] = make_uint2(packh2(__float2half_rn(v.x), __float2half_rn(v.y)),
                        packh2(__float2half_rn(v.z), __float2half_rn(v.w)));
}

__global__ __launch_bounds__(256) void conv_half_split(
    const float4* __restrict__ src, uint2* __restrict__ hi, uint2* __restrict__ lo, int n4)
{
    int i = blockIdx.x * 256 + threadIdx.x;
    if (i >= n4) return;
    float4 v = src[i];
    __half h0 = __float2half_rn(v.x);
    __half h1 = __float2half_rn(v.y);
    __half h2 = __float2half_rn(v.z);
    __half h3 = __float2half_rn(v.w);
    hi[i] = make_uint2(packh2(h0, h1), packh2(h2, h3));
    __half l0 = __float2half_rn(v.x - __half2float(h0));
    __half l1 = __float2half_rn(v.y - __half2float(h1));
    __half l2 = __float2half_rn(v.z - __half2float(h2));
    __half l3 = __float2half_rn(v.w - __half2float(h3));
    lo[i] = make_uint2(packh2(l0, l1), packh2(l2, l3));
}

__global__ __launch_bounds__(256) void conv_wspk(
    const float* __restrict__ W, uint2* __restrict__ hi, uint2* __restrict__ lo)
{
    int idx = blockIdx.x * 256 + threadIdx.x;
    if (idx >= 300 * (KGEN / 4)) return;
    int row = idx / (KGEN / 4);
    int c4 = idx - row * (KGEN / 4);
    float v[4];
    #pragma unroll
    for (int q = 0; q < 4; q++) {
        int k = c4 * 4 + q;
        v[q] = (k < UDIM + FDIM) ? W[row * (UDIM + FDIM) + k] : 0.f;
    }
    __half h0 = __float2half_rn(v[0]), h1 = __float2half_rn(v[1]);
    __half h2 = __float2half_rn(v[2]), h3 = __float2half_rn(v[3]);
    hi[idx] = make_uint2(packh2(h0, h1), packh2(h2, h3));
    __half l0 = __float2half_rn(v[0] - __half2float(h0));
    __half l1 = __float2half_rn(v[1] - __half2float(h1));
    __half l2 = __float2half_rn(v[2] - __half2float(h2));
    __half l3 = __float2half_rn(v[3] - __half2float(h3));
    lo[idx] = make_uint2(packh2(l0, l1), packh2(l2, l3));
}

// =================================================================================
// shared PTX helpers
// =================================================================================
__device__ __forceinline__ uint32_t smem_u32(const void* p) {
    uint32_t a;
    asm("{ .reg .u64 t; cvta.to.shared.u64 t, %1; cvt.u32.u64 %0, t; }" : "=r"(a) : "l"(p));
    return a;
}

__device__ __forceinline__ void ldm_x4(uint32_t* r, uint32_t addr) {
    asm volatile("ldmatrix.sync.aligned.m8n8.x4.shared.b16 {%0,%1,%2,%3}, [%4];"
                 : "=r"(r[0]), "=r"(r[1]), "=r"(r[2]), "=r"(r[3]) : "r"(addr));
}

__device__ __forceinline__ void mma_fp16(float* d, const uint32_t* a, uint32_t b0, uint32_t b1) {
    asm volatile(
        "mma.sync.aligned.m16n8k16.row.col.f32.f16.f16.f32 "
        "{%0,%1,%2,%3}, {%4,%5,%6,%7}, {%8,%9}, {%0,%1,%2,%3};"
        : "+f"(d[0]), "+f"(d[1]), "+f"(d[2]), "+f"(d[3])
        : "r"(a[0]), "r"(a[1]), "r"(a[2]), "r"(a[3]), "r"(b0), "r"(b1));
}

// =================================================================================
// Tensor-core GEMM (unchanged from R15 — passing, 124us/launch)
// =================================================================================
#define BKT 64
#define TPAD 72
#define TILE_B (128 * TPAD * 2)
#define STAGE_B (3 * TILE_B)
#define SMG_BASE 1024
#define GEMM_SMEM (SMG_BASE + 2 * STAGE_B)

__device__ __forceinline__ void cp_tile(
    const __half* __restrict__ src, int stride, int row0,
    int kbase, int kmax, uint32_t smDst, int tid)
{
    #pragma unroll
    for (int i = 0; i < 8; i++) {
        int idx = i * 256 + tid;
        int r = idx >> 4, c4 = idx & 15;
        int kg = kbase + c4 * 4;
        int sz = (kg < kmax) ? 8 : 0;
        int kgc = (kg < kmax) ? kg : 0;
        size_t off = (size_t)(row0 + r) * stride + kgc;
        uint32_t so = (uint32_t)(r * TPAD + c4 * 4) * 2;
        asm volatile("cp.async.ca.shared.global [%0], [%1], 8, %2;"
                     :: "r"(smDst + so), "l"(src + off), "r"(sz));
    }
}

__global__ __launch_bounds__(256, 2) void gemm_mma(
    const uint2* Ah0u, int K0, const uint2* Ah1u, int K1,
    const uint2* Whiu, const uint2* Wlou,
    const float* __restrict__ bias, float* __restrict__ C, int reverse,
    int cstride, int cmax)
{
    extern __shared__ char sm[];
    const __half* Ah0 = (const __half*)Ah0u;
    const __half* Ah1 = (const __half*)Ah1u;
    const __half* Whi = (const __half*)Whiu;
    const __half* Wlo = (const __half*)Wlou;

    const int tid  = threadIdx.x;
    const int warp = tid >> 5, lane = tid & 31;
    const int tb = blockIdx.x;
    const int n0 = blockIdx.y * 128;
    const int Ktot = K0 + K1;
    const int nkt = (Ktot + BKT - 1) / BKT;

    const int m0w = (warp >> 1) * 32;
    const int n0w = (warp & 1) * 64;
    const int laneRow  = lane & 15;
    const int laneHalf = lane >> 4;

    float* biass = (float*)sm;
    if (tid < 128) biass[tid] = bias[n0 + tid];

    const int arow0 = (reverse ? (T_STEPS - 1 - tb) : tb) * BATCH;
    const int crow0 = tb * BATCH;

    const uint32_t smBase = smem_u32(sm + SMG_BASE);

    float acc[2][8][4];
    #pragma unroll
    for (int mi = 0; mi < 2; mi++)
        #pragma unroll
        for (int nf = 0; nf < 8; nf++)
            #pragma unroll
            for (int q = 0; q < 4; q++) acc[mi][nf][q] = 0.f;

    auto issue_tile = [&](int kt) {
        const int k0 = kt * BKT;
        const uint32_t stg = smBase + (uint32_t)(kt & 1) * STAGE_B;
        if (k0 < K0)
            cp_tile(Ah0, K0, arow0, k0, K0, stg, tid);
        else
            cp_tile(Ah1, K1, arow0, k0 - K0, K1, stg, tid);
        cp_tile(Whi, Ktot, n0, k0, Ktot, stg + TILE_B, tid);
        cp_tile(Wlo, Ktot, n0, k0, Ktot, stg + 2 * TILE_B, tid);
    };

    issue_tile(0);
    asm volatile("cp.async.commit_group;" ::: "memory");

    for (int kt = 0; kt < nkt; kt++) {
        if (kt + 1 < nkt) issue_tile(kt + 1);
        asm volatile("cp.async.commit_group;" ::: "memory");
        asm volatile("cp.async.wait_group 1;" ::: "memory");
        __syncthreads();

        const uint32_t stg = smBase + (uint32_t)(kt & 1) * STAGE_B;
        const uint32_t sbA   = stg;
        const uint32_t sbBHI = stg + TILE_B;
        const uint32_t sbBLO = stg + 2 * TILE_B;

        #pragma unroll
        for (int ks = 0; ks < 4; ks++) {
            const uint32_t colb = (uint32_t)(ks * 16 + laneHalf * 8) * 2;

            uint32_t ah[2][4];
            #pragma unroll
            for (int mi = 0; mi < 2; mi++) {
                uint32_t ro = (uint32_t)(m0w + mi * 16 + laneRow) * (TPAD * 2) + colb;
                ldm_x4(ah[mi], sbA + ro);
            }
            uint32_t bh[8][2], bl[8][2];
            #pragma unroll
            for (int ni = 0; ni < 4; ni++) {
                uint32_t ro = (uint32_t)(n0w + ni * 16 + laneRow) * (TPAD * 2) + colb;
                uint32_t rb[4];
                ldm_x4(rb, sbBHI + ro);
                bh[2 * ni][0] = rb[0]; bh[2 * ni][1] = rb[2];
                bh[2 * ni + 1][0] = rb[1]; bh[2 * ni + 1][1] = rb[3];
                ldm_x4(rb, sbBLO + ro);
                bl[2 * ni][0] = rb[0]; bl[2 * ni][1] = rb[2];
                bl[2 * ni + 1][0] = rb[1]; bl[2 * ni + 1][1] = rb[3];
            }
            #pragma unroll
            for (int mi = 0; mi < 2; mi++)
                #pragma unroll
                for (int nf = 0; nf < 8; nf++)
                    mma_fp16(acc[mi][nf], ah[mi], bh[nf][0], bh[nf][1]);
            #pragma unroll
            for (int mi = 0; mi < 2; mi++)
                #pragma unroll
                for (int nf = 0; nf < 8; nf++)
                    mma_fp16(acc[mi][nf], ah[mi], bl[nf][0], bl[nf][1]);
        }
        __syncthreads();
    }

    float* stage = (float*)(sm + SMG_BASE);
    {
        const int g = lane >> 2, t4 = lane & 3;
        #pragma unroll
        for (int mi = 0; mi < 2; mi++)
            #pragma unroll
            for (int nf = 0; nf < 8; nf++) {
                int col = n0w + nf * 8 + 2 * t4;
                float* p0 = &stage[(m0w + mi * 16 + g) * 132 + col];
                float* p1 = &stage[(m0w + mi * 16 + g + 8) * 132 + col];
                p0[0] = acc[mi][nf][0]; p0[1] = acc[mi][nf][1];
                p1[0] = acc[mi][nf][2]; p1[1] = acc[mi][nf][3];
            }
    }
    __syncthreads();
    {
        const int col = tid & 127;
        if (n0 + col < cmax) {
            const float bcol = biass[col];
            #pragma unroll 4
            for (int it = 0; it < 64; it++) {
                int r = it * 2 + (tid >> 7);
                C[(size_t)(crow0 + r) * cstride + n0 + col] = stage[r * 132 + col] + bcol;
            }
        }
    }
}

// =================================================================================
// Tensor-core GRU scans: hh = Whh @ [h0|h1] as per-step mma.
//   A (Whh hi/lo) fragments resident in registers; B = h hi/lo fp16 tile in smem.
//   Two accumulating passes into one C give exact (Whi+Wlo)(hhi+hlo) = W·h.
// =================================================================================
#define HSTR  136                      // halves per Hmat/staging row
#define HSTRB (HSTR * 2)               // 272 bytes
#define SCAN_STAGE_B (G3E * HSTRB)     // 104448 bytes (A staging)
#define HM_B   (16 * HSTRB)            // 4352
#define SCAN_SMEM SCAN_STAGE_B

__device__ __forceinline__ void stageW(const uint2* __restrict__ W, char* sm, int tid) {
    for (int i = tid; i < WHN4; i += 384) {
        int row = i >> 5, c4 = i & 31;
        *(uint2*)(sm + row * HSTRB + c4 * 8) = W[i];
    }
}

// shared scan body via macro-free duplication (enc / ctrl differ in I/O only)

__global__ __launch_bounds__(384, 1) void enc_scan(
    const uint2* __restrict__ Wfh, const uint2* __restrict__ Wfl,
    const uint2* __restrict__ Wbh, const uint2* __restrict__ Wbl,
    const float* __restrict__ bhh_f, const float* __restrict__ bhh_b,
    const float* __restrict__ enc_init)
{
    extern __shared__ char sm[];
    const int tid = threadIdx.x;
    const int warp = tid >> 5, lane = tid & 31;
    const int laneRow = lane & 15, laneHalf = lane >> 4;
    const int dir = blockIdx.x >> 6;
    const int b0 = (blockIdx.x & 63) * 2;
    const uint2* Whi = dir ? Wbh : Wfh;
    const uint2* Wlo = dir ? Wbl : Wfl;
    const float* bhh = dir ? bhh_b : bhh_f;
    const float* xp = dir ? g_xpb : g_xpf;

    const uint32_t smB = smem_u32(sm);

    // load A fragments (once)
    uint32_t awhi[2][8][4], awlo[2][8][4];
    stageW(Whi, sm, tid);
    __syncthreads();
    #pragma unroll
    for (int mi = 0; mi < 2; mi++)
        #pragma unroll
        for (int ks = 0; ks < 8; ks++)
            ldm_x4(awhi[mi][ks], smB + (uint32_t)(warp * 32 + mi * 16 + laneRow) * HSTRB
                                     + (uint32_t)(ks * 16 + laneHalf * 8) * 2);
    __syncthreads();
    stageW(Wlo, sm, tid);
    __syncthreads();
    #pragma unroll
    for (int mi = 0; mi < 2; mi++)
        #pragma unroll
        for (int ks = 0; ks < 8; ks++)
            ldm_x4(awlo[mi][ks], smB + (uint32_t)(warp * 32 + mi * 16 + laneRow) * HSTRB
                                     + (uint32_t)(ks * 16 + laneHalf * 8) * 2);
    __syncthreads();

    // runtime smem layout
    __half* hm   = (__half*)sm;                 // 16 x HSTR
    float* hh0_s = (float*)(sm + HM_B);         // 384
    float* hh1_s = (float*)(sm + HM_B + 1536);  // 384
    float* bsh   = (float*)(sm + HM_B + 3072);  // 384

    for (int i = tid; i < HM_B / 4; i += 384) ((uint32_t*)sm)[i] = 0;
    __syncthreads();
    bsh[tid] = bhh[tid];

    const int jj = tid & 127;
    const int jh = (tid >> 7) & 1;              // 0: row b0, 1: row b0+1
    const int myb = b0 + jh;
    float hreg = 0.f, pr = 0.f, pz = 0.f, pn = 0.f;
    if (tid < 256) {
        hreg = enc_init[dir * 128 + jj];
        __half hhi = __float2half_rn(hreg);
        hm[jh * HSTR + jj] = hhi;
        hm[(2 + jh) * HSTR + jj] = __float2half_rn(hreg - __half2float(hhi));
        const float* xr = xp + (size_t)myb * G3E;
        pr = xr[jj]; pz = xr[128 + jj]; pn = xr[256 + jj];
    }
    __syncthreads();

    for (int t = 0; t < T_STEPS; t++) {
        // dot via tensor core
        float acc[2][4];
        #pragma unroll
        for (int mi = 0; mi < 2; mi++)
            #pragma unroll
            for (int q = 0; q < 4; q++) acc[mi][q] = 0.f;
        #pragma unroll
        for (int ks = 0; ks < 8; ks++) {
            uint32_t rb[4];
            ldm_x4(rb, smB + (uint32_t)laneRow * HSTRB + (uint32_t)(ks * 16 + laneHalf * 8) * 2);
            #pragma unroll
            for (int mi = 0; mi < 2; mi++) {
                mma_fp16(acc[mi], awhi[mi][ks], rb[0], rb[2]);
                mma_fp16(acc[mi], awlo[mi][ks], rb[0], rb[2]);
            }
        }
        // epilogue: fold hi/lo columns, store hh + bias
        #pragma unroll
        for (int mi = 0; mi < 2; mi++) {
            float s0 = acc[mi][0] + __shfl_xor_sync(0xffffffffu, acc[mi][0], 1);
            float s1 = acc[mi][1] + __shfl_xor_sync(0xffffffffu, acc[mi][1], 1);
            float s2 = acc[mi][2] + __shfl_xor_sync(0xffffffffu, acc[mi][2], 1);
            float s3 = acc[mi][3] + __shfl_xor_sync(0xffffffffu, acc[mi][3], 1);
            if ((lane & 3) == 0) {
                int r0 = warp * 32 + mi * 16 + (lane >> 2);
                int r1 = r0 + 8;
                hh0_s[r0] = bsh[r0] + s0;
                hh1_s[r0] = bsh[r0] + s1;
                hh0_s[r1] = bsh[r1] + s2;
                hh1_s[r1] = bsh[r1] + s3;
            }
        }
        __syncthreads();

        if (tid < 256) {
            float npr = 0.f, npz = 0.f, npn = 0.f;
            if (t + 1 < T_STEPS) {
                const float* xr = xp + ((size_t)(t + 1) * BATCH + myb) * G3E;
                npr = xr[jj]; npz = xr[128 + jj]; npn = xr[256 + jj];
            }
            const float* hh = jh ? hh1_s : hh0_s;
            float r = sigmf(pr + hh[jj]);
            float z = sigmf(pz + hh[128 + jj]);
            float n = tanhf_fast(pn + r * hh[256 + jj]);
            hreg = (1.f - z) * n + z * hreg;
            float gc = fminf(fmaxf(hreg, -CLIPV), CLIPV);
            int tt = dir ? (T_STEPS - 1 - t) : t;
            g_g[((size_t)tt * BATCH + myb) * (2 * EDIM) + dir * EDIM + jj] = gc;
            __half hhi = __float2half_rn(hreg);
            hm[jh * HSTR + jj] = hhi;
            hm[(2 + jh) * HSTR + jj] = __float2half_rn(hreg - __half2float(hhi));
            pr = npr; pz = npz; pn = npn;
        }
        __syncthreads();
    }
}

__global__ __launch_bounds__(384, 1) void ctrl_scan(
    const uint2* __restrict__ Wch, const uint2* __restrict__ Wcl,
    const float* __restrict__ bhh, const float* __restrict__ cinit)
{
    extern __shared__ char sm[];
    const int tid = threadIdx.x;
    const int warp = tid >> 5, lane = tid & 31;
    const int laneRow = lane & 15, laneHalf = lane >> 4;
    const int b0 = blockIdx.x * 2;

    const uint32_t smB = smem_u32(sm);

    uint32_t awhi[2][8][4], awlo[2][8][4];
    stageW(Wch, sm, tid);
    __syncthreads();
    #pragma unroll
    for (int mi = 0; mi < 2; mi++)
        #pragma unroll
        for (int ks = 0; ks < 8; ks++)
            ldm_x4(awhi[mi][ks], smB + (uint32_t)(warp * 32 + mi * 16 + laneRow) * HSTRB
                                     + (uint32_t)(ks * 16 + laneHalf * 8) * 2);
    __syncthreads();
    stageW(Wcl, sm, tid);
    __syncthreads();
    #pragma unroll
    for (int mi = 0; mi < 2; mi++)
        #pragma unroll
        for (int ks = 0; ks < 8; ks++)
            ldm_x4(awlo[mi][ks], smB + (uint32_t)(warp * 32 + mi * 16 + laneRow) * HSTRB
                                     + (uint32_t)(ks * 16 + laneHalf * 8) * 2);
    __syncthreads();

    __half* hm   = (__half*)sm;
    float* hh0_s = (float*)(sm + HM_B);
    float* hh1_s = (float*)(sm + HM_B + 1536);
    float* bsh   = (float*)(sm + HM_B + 3072);

    for (int i = tid; i < HM_B / 4; i += 384) ((uint32_t*)sm)[i] = 0;
    __syncthreads();
    bsh[tid] = bhh[tid];

    const int jj = tid & 127;
    const int jh = (tid >> 7) & 1;
    const int myb = b0 + jh;
    __half* hf = (__half*)g_hfu;
    float hreg = 0.f, pr = 0.f, pz = 0.f, pn = 0.f;
    if (tid < 256) {
        hreg = cinit[jj];
        __half hhi = __float2half_rn(hreg);
        hm[jh * HSTR + jj] = hhi;
        hm[(2 + jh) * HSTR + jj] = __float2half_rn(hreg - __half2float(hhi));
        const float* cpr = g_cp + (size_t)myb * G3E;
        pr = cpr[jj]; pz = cpr[128 + jj]; pn = cpr[256 + jj];
    }
    __syncthreads();

    for (int t = 0; t < T_STEPS; t++) {
        float acc[2][4];
        #pragma unroll
        for (int mi = 0; mi < 2; mi++)
            #pragma unroll
            for (int q = 0; q < 4; q++) acc[mi][q] = 0.f;
        #pragma unroll
        for (int ks = 0; ks < 8; ks++) {
            uint32_t rb[4];
            ldm_x4(rb, smB + (uint32_t)laneRow * HSTRB + (uint32_t)(ks * 16 + laneHalf * 8) * 2);
            #pragma unroll
            for (int mi = 0; mi < 2; mi++) {
                mma_fp16(acc[mi], awhi[mi][ks], rb[0], rb[2]);
                mma_fp16(acc[mi], awlo[mi][ks], rb[0], rb[2]);
            }
        }
        #pragma unroll
        for (int mi = 0; mi < 2; mi++) {
            float s0 = acc[mi][0] + __shfl_xor_sync(0xffffffffu, acc[mi][0], 1);
            float s1 = acc[mi][1] + __shfl_xor_sync(0xffffffffu, acc[mi][1], 1);
            float s2 = acc[mi][2] + __shfl_xor_sync(0xffffffffu, acc[mi][2], 1);
            float s3 = acc[mi][3] + __shfl_xor_sync(0xffffffffu, acc[mi][3], 1);
            if ((lane & 3) == 0) {
                int r0 = warp * 32 + mi * 16 + (lane >> 2);
                int r1 = r0 + 8;
                hh0_s[r0] = bsh[r0] + s0;
                hh1_s[r0] = bsh[r0] + s1;
                hh0_s[r1] = bsh[r1] + s2;
                hh1_s[r1] = bsh[r1] + s3;
            }
        }
        __syncthreads();

        if (tid < 256) {
            size_t row = (size_t)t * BATCH + myb;
            float npr = 0.f, npz = 0.f, npn = 0.f;
            if (t + 1 < T_STEPS) {
                const float* cpr = g_cp + (row + BATCH) * G3E;
                npr = cpr[jj]; npz = cpr[128 + jj]; npn = cpr[256 + jj];
            }
            const float* hh = jh ? hh1_s : hh0_s;
            float r = sigmf(pr + hh[jj]);
            float z = sigmf(pz + hh[128 + jj]);
            float n = tanhf_fast(pn + r * hh[256 + jj]);
            float h = (1.f - z) * n + z * hreg;
            h = fminf(fmaxf(h, -CLIPV), CLIPV);
            hreg = h;
            __half hhi = __float2half_rn(h);
            hf[row * CDIM + jj] = hhi;
            hm[jh * HSTR + jj] = hhi;
            hm[(2 + jh) * HSTR + jj] = __float2half_rn(h - __half2float(hhi));
            pr = npr; pz = npz; pn = npn;
        }
        __syncthreads();
    }
}

// ---------------------------------------------------------------------------------
// gen + calcium (unchanged from R15)
// ---------------------------------------------------------------------------------
__global__ __launch_bounds__(256) void gen_kernel(
    const float* __restrict__ mlv, const float* __restrict__ eps,
    const float* __restrict__ factors,
    const float* __restrict__ bmu, const float* __restrict__ blv)
{
    int idx = blockIdx.x * 256 + threadIdx.x;
    if (idx >= NROWS * KGEN) return;
    int row = idx / KGEN;
    int j = idx - row * KGEN;
    float v = 0.f;
    if (j < UDIM) {
        float mu = mlv[(size_t)row * 128 + j] + bmu[j];
        float lv = mlv[(size_t)row * 128 + UDIM + j] + blv[j];
        v = mu + __expf(0.5f * lv) * eps[(size_t)row * UDIM + j];
    } else if (j < UDIM + FDIM) {
        v = factors[(size_t)row * FDIM + (j - UDIM)];
    }
    ((__half*)g_genh)[idx] = __float2half_rn(v);
}

__global__ __launch_bounds__(128) void calcium_kernel(
    const float* __restrict__ logits, const float* __restrict__ bspk,
    const float* __restrict__ gain_p, const float* __restrict__ biasp_p,
    const float* __restrict__ ltau_p, float* __restrict__ out)
{
    int idx = blockIdx.x * 128 + threadIdx.x;
    if (idx >= BATCH * NIN) return;
    const int n = idx % NIN;
    const float bsp = bspk[n];
    const float gain = gain_p[0];
    const float biasp = biasp_p[0];
    const float decay = 1.f - expf(-ltau_p[0]);
    float cal = 0.f;
    const size_t stride = (size_t)BATCH * NIN;
    const float* lp = logits + idx;
    float* op = out + idx;
    for (int t = 0; t < T_STEPS; t += 4) {
        float l0 = lp[(size_t)(t + 0) * stride];
        float l1 = lp[(size_t)(t + 1) * stride];
        float l2 = lp[(size_t)(t + 2) * stride];
        float l3 = lp[(size_t)(t + 3) * stride];
        float s;
        s = fmaxf(__expf(l0 + bsp) - 1.f, 0.f); cal = cal * decay + gain * s + biasp;
        op[(size_t)(t + 0) * stride] = cal;
        s = fmaxf(__expf(l1 + bsp) - 1.f, 0.f); cal = cal * decay + gain * s + biasp;
        op[(size_t)(t + 1) * stride] = cal;
        s = fmaxf(__expf(l2 + bsp) - 1.f, 0.f); cal = cal * decay + gain * s + biasp;
        op[(size_t)(t + 2) * stride] = cal;
        s = fmaxf(__expf(l3 + bsp) - 1.f, 0.f); cal = cal * decay + gain * s + biasp;
        op[(size_t)(t + 3) * stride] = cal;
    }
}

// ---------------------------------------------------------------------------------
extern "C" void kernel_launch(void* const* d_in, const int* in_sizes, int n_in,
                              void* d_out, int out_size)
{
    (void)in_sizes; (void)n_in; (void)out_size;
    const float* x       = (const float*)d_in[0];
    const float* factors = (const float*)d_in[1];
    const float* eps     = (const float*)d_in[2];
    const float* eWihf   = (const float*)d_in[3];
    const float* eWhhf   = (const float*)d_in[4];
    const float* ebihf   = (const float*)d_in[5];
    const float* ebhhf   = (const float*)d_in[6];
    const float* eWihb   = (const float*)d_in[7];
    const float* eWhhb   = (const float*)d_in[8];
    const float* ebihb   = (const float*)d_in[9];
    const float* ebhhb   = (const float*)d_in[10];
    const float* einit   = (const float*)d_in[11];
    const float* cWih    = (const float*)d_in[12];
    const float* cWhh    = (const float*)d_in[13];
    const float* cbih    = (const float*)d_in[14];
    const float* cbhh    = (const float*)d_in[15];
    const float* cinit   = (const float*)d_in[16];
    const float* Wmu     = (const float*)d_in[17];
    const float* bmu     = (const float*)d_in[18];
    const float* Wlv     = (const float*)d_in[19];
    const float* blv     = (const float*)d_in[20];
    const float* Wspk    = (const float*)d_in[21];
    const float* bspk    = (const float*)d_in[22];
    const float* gain    = (const float*)d_in[23];
    const float* bp      = (const float*)d_in[24];
    const float* ltau    = (const float*)d_in[25];
    float* out = (float*)d_out;

    float *xpf, *xpb, *gg, *cp, *zero;
    cudaGetSymbolAddress((void**)&xpf, g_xpf);
    cudaGetSymbolAddress((void**)&xpb, g_xpb);
    cudaGetSymbolAddress((void**)&gg,  g_g);
    cudaGetSymbolAddress((void**)&cp,  g_cp);
    cudaGetSymbolAddress((void**)&zero, g_zero);

    uint2 *xh, *gh, *wfh, *wfl, *wbh, *wbl, *wch, *wcl, *wmh, *wml, *wsh, *wsl;
    uint2 *wWfh, *wWfl, *wWbh, *wWbl, *wWch, *wWcl, *hfu, *genh;
    cudaGetSymbolAddress((void**)&xh, g_xh);
    cudaGetSymbolAddress((void**)&gh, g_gh);
    cudaGetSymbolAddress((void**)&wfh, g_wfh); cudaGetSymbolAddress((void**)&wfl, g_wfl);
    cudaGetSymbolAddress((void**)&wbh, g_wbh); cudaGetSymbolAddress((void**)&wbl, g_wbl);
    cudaGetSymbolAddress((void**)&wch, g_wch); cudaGetSymbolAddress((void**)&wcl, g_wcl);
    cudaGetSymbolAddress((void**)&wmh, g_wmh); cudaGetSymbolAddress((void**)&wml, g_wml);
    cudaGetSymbolAddress((void**)&wsh, g_wsh); cudaGetSymbolAddress((void**)&wsl, g_wsl);
    cudaGetSymbolAddress((void**)&wWfh, g_wWfh); cudaGetSymbolAddress((void**)&wWfl, g_wWfl);
    cudaGetSymbolAddress((void**)&wWbh, g_wWbh); cudaGetSymbolAddress((void**)&wWbl, g_wWbl);
    cudaGetSymbolAddress((void**)&wWch, g_wWch); cudaGetSymbolAddress((void**)&wWcl, g_wWcl);
    cudaGetSymbolAddress((void**)&hfu, g_hfu);
    cudaGetSymbolAddress((void**)&genh, g_genh);

    cudaFuncSetAttribute(gemm_mma, cudaFuncAttributeMaxDynamicSharedMemorySize, GEMM_SMEM);
    cudaFuncSetAttribute(enc_scan, cudaFuncAttributeMaxDynamicSharedMemorySize, SCAN_SMEM);
    cudaFuncSetAttribute(ctrl_scan, cudaFuncAttributeMaxDynamicSharedMemorySize, SCAN_SMEM);

    dim3 gemm_grid(T_STEPS, G3E / 128);

    // conversions
    conv_half<<<(XN4 + 255) / 256, 256>>>((const float4*)x, xh, XN4);
    conv_half_split<<<(WFN4 + 255) / 256, 256>>>((const float4*)eWihf, wfh, wfl, WFN4);
    conv_half_split<<<(WFN4 + 255) / 256, 256>>>((const float4*)eWihb, wbh, wbl, WFN4);
    conv_half_split<<<(WHN4 + 255) / 256, 256>>>((const float4*)eWhhf, wWfh, wWfl, WHN4);
    conv_half_split<<<(WHN4 + 255) / 256, 256>>>((const float4*)eWhhb, wWbh, wWbl, WHN4);

    // input-projection GEMMs
    gemm_mma<<<gemm_grid, 256, GEMM_SMEM>>>(xh, NIN, nullptr, 0, wfh, wfl, ebihf, xpf, 0, G3E, G3E);
    gemm_mma<<<gemm_grid, 256, GEMM_SMEM>>>(xh, NIN, nullptr, 0, wbh, wbl, ebihb, xpb, 1, G3E, G3E);

    // bidirectional encoder scan (tensor-core recurrence)
    enc_scan<<<128, 384, SCAN_SMEM>>>(wWfh, wWfl, wWbh, wWbl, ebhhf, ebhhb, einit);

    // cp = [g, x] @ ctrl_Wih^T + b
    conv_half_split<<<(WCN4 + 255) / 256, 256>>>((const float4*)cWih, wch, wcl, WCN4);
    conv_half<<<(GN4 + 255) / 256, 256>>>((const float4*)gg, gh, GN4);
    gemm_mma<<<gemm_grid, 256, GEMM_SMEM>>>(gh, 2 * EDIM, xh, NIN, wch, wcl, cbih, cp, 0, G3E, G3E);

    // controller scan (tensor-core recurrence) -> h fp16
    conv_half_split<<<(WHN4 + 255) / 256, 256>>>((const float4*)cWhh, wWch, wWcl, WHN4);
    ctrl_scan<<<64, 384, SCAN_SMEM>>>(wWch, wWcl, cbhh, cinit);

    // downstream batched kernels
    conv_half_split<<<(WMN4 + 255) / 256, 256>>>((const float4*)Wmu, wmh, wml, WMN4);
    conv_half_split<<<(WMN4 + 255) / 256, 256>>>((const float4*)Wlv, wmh + WMN4, wml + WMN4, WMN4);
    conv_wspk<<<(300 * (KGEN / 4) + 255) / 256, 256>>>(Wspk, wsh, wsl);

    gemm_mma<<<dim3(T_STEPS, 1), 256, GEMM_SMEM>>>(hfu, CDIM, nullptr, 0,
                                                   wmh, wml, zero, xpf, 0, 128, 128);
    gen_kernel<<<(NROWS * KGEN + 255) / 256, 256>>>(xpf, eps, factors, bmu, blv);
    gemm_mma<<<dim3(T_STEPS, 3), 256, GEMM_SMEM>>>(genh, KGEN, nullptr, 0,
                                                   wsh, wsl, zero, xpb, 0, NIN, NIN);
    calcium_kernel<<<(BATCH * NIN + 127) / 128, 128>>>(xpb, bspk, gain, bp, ltau, out);
}